// round 6
// baseline (speedup 1.0000x reference)
#include <cuda_runtime.h>
#include <math.h>
#include <stdint.h>

// ---------------------------------------------------------------------------
// WSFAttention: wavelet attention. GEMMs on tensor pipe via mma.sync tf32
// with 3xTF32 split for fp32-grade accuracy.
// Shapes: B=8, L=4096 (64x64), C=384, NH=3, n=1024 (32x32), d=384.
// ---------------------------------------------------------------------------

constexpr long Bb    = 8;
constexpr long Ll    = 4096;
constexpr long Nn    = 1024;
constexpr long Mrows = Bb * Ll;

constexpr long T1_OFF = 0;                         constexpr long T1_SZ = Mrows * 384;
constexpr long T2_OFF = T1_OFF + T1_SZ;            constexpr long T2_SZ = Mrows * 768;
constexpr long Q1_OFF = T2_OFF + T2_SZ;            constexpr long Q1_SZ = Bb * Nn * 384;
constexpr long Q2_OFF = Q1_OFF + Q1_SZ;            constexpr long Q2_SZ = Bb * Nn * 1152;
constexpr long K1_OFF = Q2_OFF + Q2_SZ;            constexpr long K1_SZ = Bb * Nn * 384;
constexpr long K2_OFF = K1_OFF + K1_SZ;            constexpr long K2_SZ = Bb * Nn * 1152;
constexpr long V1_OFF = K2_OFF + K2_SZ;            constexpr long V1_SZ = Bb * Nn * 384;
constexpr long V2_OFF = V1_OFF + V1_SZ;            constexpr long V2_SZ = Bb * Nn * 1152;
constexpr long S_OFF  = V2_OFF + V2_SZ;            constexpr long S_SZ  = 32L * Nn * Nn;
constexpr long X1_OFF = S_OFF + S_SZ;              constexpr long X1_SZ = Bb * Nn * 384;
constexpr long X2_OFF = X1_OFF + X1_SZ;            constexpr long X2_SZ = Bb * Nn * 1152;
constexpr long TOTAL  = X2_OFF + X2_SZ;

__device__ float g_scratch[TOTAL];

// ---------------------------------------------------------------------------
__device__ __forceinline__ float warp_sum(float v) {
    #pragma unroll
    for (int o = 16; o > 0; o >>= 1) v += __shfl_xor_sync(0xffffffffu, v, o);
    return v;
}
__device__ __forceinline__ float warp_max(float v) {
    #pragma unroll
    for (int o = 16; o > 0; o >>= 1) v = fmaxf(v, __shfl_xor_sync(0xffffffffu, v, o));
    return v;
}

// ---------------------------------------------------------------------------
// tensor-core primitives
// ---------------------------------------------------------------------------
__device__ __forceinline__ uint32_t smem_u32(const void* p) {
    return (uint32_t)__cvta_generic_to_shared(p);
}
__device__ __forceinline__ void ldsm4(uint32_t* r, uint32_t a) {
    asm volatile("ldmatrix.sync.aligned.m8n8.x4.shared.b16 {%0,%1,%2,%3}, [%4];"
        : "=r"(r[0]), "=r"(r[1]), "=r"(r[2]), "=r"(r[3]) : "r"(a));
}
__device__ __forceinline__ void mma8(float* c, const uint32_t* a, const uint32_t* b) {
    asm volatile("mma.sync.aligned.m16n8k8.row.col.f32.tf32.tf32.f32 "
        "{%0,%1,%2,%3},{%4,%5,%6,%7},{%8,%9},{%0,%1,%2,%3};"
        : "+f"(c[0]), "+f"(c[1]), "+f"(c[2]), "+f"(c[3])
        : "r"(a[0]), "r"(a[1]), "r"(a[2]), "r"(a[3]), "r"(b[0]), "r"(b[1]));
}
// split fp32 into hi/lo tf32 pair: v ~= hi + lo, each exactly representable in tf32
__device__ __forceinline__ void split1(float v, uint32_t& h, uint32_t& l) {
    uint32_t hu; asm("cvt.rna.tf32.f32 %0, %1;" : "=r"(hu) : "f"(v));
    float hf = __uint_as_float(hu);
    float lf = v - hf;
    uint32_t lu; asm("cvt.rna.tf32.f32 %0, %1;" : "=r"(lu) : "f"(lf));
    h = hu; l = lu;
}

// ---------------------------------------------------------------------------
// Tensor-core tiled GEMM (3xTF32).
//   C[m,n] = alpha * sum_k opA(A)[m,k] * opB(B)[k,n]  (+ bias[n])
//   TA: A stored (K, M) row-major; else (M, K).
//   TB: B stored (N, K) row-major; else (K, N).
// Block tile 128x128x16, 256 threads (8 warps of 64x32).
// Requires M%128==0, N%128==0, K%16==0, strides %4, 16B-aligned bases.
// Batched over blockIdx.z as before.
// ---------------------------------------------------------------------------
#define SROW 20   // smem row stride in u32 (16 + 4 pad) -> 80B, LDSM conflict-free

template<bool TA, bool TB, bool BIAS>
__global__ __launch_bounds__(256) void gemm_tc(
    const float* __restrict__ A, const float* __restrict__ B,
    float* __restrict__ Cp, const float* __restrict__ bias,
    int M, int N, int K, int lda, int ldb, int ldc, float alpha,
    int nh, long bsA, long hsA, long bsB, long hsB, long bsC, long hsC)
{
    const int z  = blockIdx.z;
    const int bbi = z / nh, hh = z % nh;
    A  += bbi * bsA + hh * hsA;
    B  += bbi * bsB + hh * hsB;
    Cp += bbi * bsC + hh * hsC;

    __shared__ uint32_t Ah[128 * SROW], Al[128 * SROW];
    __shared__ uint32_t Bh[128 * SROW], Bl[128 * SROW];

    const int tid  = threadIdx.x;
    const int lane = tid & 31;
    const int warp = tid >> 5;
    const int wm = (warp & 1) * 64;    // warp m offset in tile
    const int wn = (warp >> 1) * 32;   // warp n offset in tile
    const long m0 = (long)blockIdx.y * 128;
    const long n0 = (long)blockIdx.x * 128;

    float4 pa[2], pb[2];

    auto loadA = [&](int k0) {
        #pragma unroll
        for (int j = 0; j < 2; j++) {
            const int i = tid + j * 256;
            if (!TA) {
                const int r = i >> 2, c = (i & 3) << 2;
                pa[j] = *reinterpret_cast<const float4*>(A + (m0 + r) * lda + k0 + c);
            } else {
                const int kk = i >> 5, mc = (i & 31) << 2;
                pa[j] = *reinterpret_cast<const float4*>(A + (long)(k0 + kk) * lda + m0 + mc);
            }
        }
    };
    auto loadB = [&](int k0) {
        #pragma unroll
        for (int j = 0; j < 2; j++) {
            const int i = tid + j * 256;
            if (TB) {
                const int r = i >> 2, c = (i & 3) << 2;
                pb[j] = *reinterpret_cast<const float4*>(B + (n0 + r) * ldb + k0 + c);
            } else {
                const int kk = i >> 5, nc = (i & 31) << 2;
                pb[j] = *reinterpret_cast<const float4*>(B + (long)(k0 + kk) * ldb + n0 + nc);
            }
        }
    };
    auto storeA = [&]() {
        #pragma unroll
        for (int j = 0; j < 2; j++) {
            const int i = tid + j * 256;
            float v[4] = {pa[j].x, pa[j].y, pa[j].z, pa[j].w};
            if (!TA) {
                const int r = i >> 2, c = (i & 3) << 2;
                #pragma unroll
                for (int e = 0; e < 4; e++) {
                    uint32_t h, l; split1(v[e], h, l);
                    Ah[r * SROW + c + e] = h; Al[r * SROW + c + e] = l;
                }
            } else {
                const int kk = i >> 5, mc = (i & 31) << 2;
                #pragma unroll
                for (int e = 0; e < 4; e++) {
                    uint32_t h, l; split1(v[e], h, l);
                    Ah[(mc + e) * SROW + kk] = h; Al[(mc + e) * SROW + kk] = l;
                }
            }
        }
    };
    auto storeB = [&]() {
        #pragma unroll
        for (int j = 0; j < 2; j++) {
            const int i = tid + j * 256;
            float v[4] = {pb[j].x, pb[j].y, pb[j].z, pb[j].w};
            if (TB) {
                const int r = i >> 2, c = (i & 3) << 2;
                #pragma unroll
                for (int e = 0; e < 4; e++) {
                    uint32_t h, l; split1(v[e], h, l);
                    Bh[r * SROW + c + e] = h; Bl[r * SROW + c + e] = l;
                }
            } else {
                const int kk = i >> 5, nc = (i & 31) << 2;
                #pragma unroll
                for (int e = 0; e < 4; e++) {
                    uint32_t h, l; split1(v[e], h, l);
                    Bh[(nc + e) * SROW + kk] = h; Bl[(nc + e) * SROW + kk] = l;
                }
            }
        }
    };

    // ldmatrix per-lane source rows:
    //  A x4 (m16 x k8): sub=lane/8 -> m += (sub&1)*8, k += (sub>>1)*4
    //  B x4 (n16 x k8): sub=lane/8 -> n += (sub>>1)*8, k += (sub&1)*4
    const uint32_t aAh = smem_u32(Ah), aAl = smem_u32(Al);
    const uint32_t aBh = smem_u32(Bh), aBl = smem_u32(Bl);
    const int a_row = wm + ((lane >> 3) & 1) * 8 + (lane & 7);
    const int a_kad = (lane >> 4) * 4;
    const uint32_t a_off = (uint32_t)(a_row * SROW + a_kad) * 4u;
    const int b_row = wn + (lane >> 4) * 8 + (lane & 7);
    const int b_kad = ((lane >> 3) & 1) * 4;
    const uint32_t b_off = (uint32_t)(b_row * SROW + b_kad) * 4u;

    float acc[4][4][4];
    #pragma unroll
    for (int i = 0; i < 4; i++)
        #pragma unroll
        for (int j = 0; j < 4; j++)
            #pragma unroll
            for (int e = 0; e < 4; e++) acc[i][j][e] = 0.f;

    const int nit = K / 16;
    loadA(0); loadB(0);
    for (int it = 0; it < nit; ++it) {
        storeA(); storeB();
        __syncthreads();
        if (it + 1 < nit) { loadA((it + 1) * 16); loadB((it + 1) * 16); }

        #pragma unroll
        for (int ks = 0; ks < 2; ks++) {
            uint32_t ah[4][4], al[4][4], bh[2][4], bl[2][4];
            #pragma unroll
            for (int mt = 0; mt < 4; mt++) {
                const uint32_t o = a_off + (uint32_t)(mt * 16 * SROW + ks * 8) * 4u;
                ldsm4(ah[mt], aAh + o);
                ldsm4(al[mt], aAl + o);
            }
            #pragma unroll
            for (int ng = 0; ng < 2; ng++) {
                const uint32_t o = b_off + (uint32_t)(ng * 16 * SROW + ks * 8) * 4u;
                ldsm4(bh[ng], aBh + o);
                ldsm4(bl[ng], aBl + o);
            }
            #pragma unroll
            for (int mt = 0; mt < 4; mt++) {
                #pragma unroll
                for (int nt = 0; nt < 4; nt++) {
                    uint32_t bfh[2] = {bh[nt >> 1][(nt & 1) * 2], bh[nt >> 1][(nt & 1) * 2 + 1]};
                    uint32_t bfl[2] = {bl[nt >> 1][(nt & 1) * 2], bl[nt >> 1][(nt & 1) * 2 + 1]};
                    mma8(acc[mt][nt], ah[mt], bfh);
                    mma8(acc[mt][nt], ah[mt], bfl);
                    mma8(acc[mt][nt], al[mt], bfh);
                }
            }
        }
        __syncthreads();
    }

    // epilogue: d0=(r,2c) d1=(r,2c+1) d2=(r+8,2c) d3=(r+8,2c+1)
    #pragma unroll
    for (int mt = 0; mt < 4; mt++) {
        const long r0 = m0 + wm + mt * 16 + (lane >> 2);
        #pragma unroll
        for (int nt = 0; nt < 4; nt++) {
            const long cc = n0 + wn + nt * 8 + (lane & 3) * 2;
            float b0 = 0.f, b1 = 0.f;
            if (BIAS) { b0 = bias[cc]; b1 = bias[cc + 1]; }
            float2 v;
            v.x = acc[mt][nt][0] * alpha + b0;
            v.y = acc[mt][nt][1] * alpha + b1;
            *reinterpret_cast<float2*>(Cp + r0 * ldc + cc) = v;
            v.x = acc[mt][nt][2] * alpha + b0;
            v.y = acc[mt][nt][3] * alpha + b1;
            *reinterpret_cast<float2*>(Cp + (r0 + 8) * ldc + cc) = v;
        }
    }
}

// ---------------------------------------------------------------------------
// Row LayerNorm (in place)
// ---------------------------------------------------------------------------
template<int W>
__global__ __launch_bounds__(128) void ln_kernel(float* __restrict__ x,
                                                 const float* __restrict__ g,
                                                 const float* __restrict__ b)
{
    constexpr int TPB = 128, PER = W / TPB;
    float* xr = x + (long)blockIdx.x * W;
    const int t = threadIdx.x;
    float v[PER];
    float s = 0.f, s2 = 0.f;
    #pragma unroll
    for (int i = 0; i < PER; i++) {
        v[i] = xr[t + i * TPB];
        s += v[i]; s2 += v[i] * v[i];
    }
    __shared__ float shA[4], shB[4];
    s = warp_sum(s); s2 = warp_sum(s2);
    if ((t & 31) == 0) { shA[t >> 5] = s; shB[t >> 5] = s2; }
    __syncthreads();
    s  = shA[0] + shA[1] + shA[2] + shA[3];
    s2 = shB[0] + shB[1] + shB[2] + shB[3];
    const float mean = s / W;
    const float var  = s2 / W - mean * mean;
    const float inv  = rsqrtf(var + 1e-5f);
    #pragma unroll
    for (int i = 0; i < PER; i++) {
        const int c = t + i * TPB;
        xr[c] = (v[i] - mean) * inv * g[c] + b[c];
    }
}

// ---------------------------------------------------------------------------
// Row softmax over 1024 columns
// ---------------------------------------------------------------------------
__global__ __launch_bounds__(256) void softmax1024(float* __restrict__ S)
{
    float* row = S + (long)blockIdx.x * 1024;
    const int t = threadIdx.x;
    float v[4];
    float mx = -1e30f;
    #pragma unroll
    for (int i = 0; i < 4; i++) { v[i] = row[t + i * 256]; mx = fmaxf(mx, v[i]); }
    __shared__ float shm[8], shs[8];
    mx = warp_max(mx);
    if ((t & 31) == 0) shm[t >> 5] = mx;
    __syncthreads();
    float rmax = shm[0];
    #pragma unroll
    for (int i = 1; i < 8; i++) rmax = fmaxf(rmax, shm[i]);
    float s = 0.f;
    #pragma unroll
    for (int i = 0; i < 4; i++) { v[i] = expf(v[i] - rmax); s += v[i]; }
    s = warp_sum(s);
    if ((t & 31) == 0) shs[t >> 5] = s;
    __syncthreads();
    float rs = 0.f;
    #pragma unroll
    for (int i = 0; i < 8; i++) rs += shs[i];
    const float inv = 1.f / rs;
    #pragma unroll
    for (int i = 0; i < 4; i++) row[t + i * 256] = v[i] * inv;
}

// ---------------------------------------------------------------------------
// DWT gathers
// ---------------------------------------------------------------------------
__global__ void dwt_sf_kernel(const float* __restrict__ t1,
                              float* __restrict__ q1, float* __restrict__ q2)
{
    long idx = (long)blockIdx.x * blockDim.x + threadIdx.x;
    if (idx >= Bb * Nn * 384) return;
    const int c = (int)(idx % 384);
    const long tt = idx / 384;
    const int p = (int)(tt % Nn);
    const int b = (int)(tt / Nn);
    const int i = p >> 5, j = p & 31;
    const long base = (long)b * Ll * 384 + c;
    const float a1 = t1[base + (long)((2 * i)     * 64 + 2 * j)     * 384];
    const float a2 = t1[base + (long)((2 * i + 1) * 64 + 2 * j)     * 384];
    const float a3 = t1[base + (long)((2 * i)     * 64 + 2 * j + 1) * 384];
    const float a4 = t1[base + (long)((2 * i + 1) * 64 + 2 * j + 1) * 384];
    const float g1 = 0.5f * ( a1 + a2 + a3 + a4);
    const float g2 = 0.5f * (-a1 - a2 + a3 + a4);
    const float g3 = 0.5f * (-a1 + a2 - a3 + a4);
    const float g4 = 0.5f * ( a1 - a2 - a3 + a4);
    q1[((long)b * Nn + p) * 384 + c] = g1;
    float* q2r = q2 + ((long)b * Nn + p) * 1152;
    q2r[c] = g2; q2r[384 + c] = g3; q2r[768 + c] = g4;
}

__global__ void dwt_wf_kernel(const float* __restrict__ t2,
                              float* __restrict__ k1, float* __restrict__ k2,
                              float* __restrict__ v1, float* __restrict__ v2)
{
    long idx = (long)blockIdx.x * blockDim.x + threadIdx.x;
    if (idx >= Bb * Nn * 768) return;
    const int c = (int)(idx % 768);
    const long tt = idx / 768;
    const int p = (int)(tt % Nn);
    const int b = (int)(tt / Nn);
    const int i = p >> 5, j = p & 31;
    const long base = (long)b * Ll * 768 + c;
    const float a1 = t2[base + (long)((2 * i)     * 64 + 2 * j)     * 768];
    const float a2 = t2[base + (long)((2 * i + 1) * 64 + 2 * j)     * 768];
    const float a3 = t2[base + (long)((2 * i)     * 64 + 2 * j + 1) * 768];
    const float a4 = t2[base + (long)((2 * i + 1) * 64 + 2 * j + 1) * 768];
    const float g1 = 0.5f * ( a1 + a2 + a3 + a4);
    const float g2 = 0.5f * (-a1 - a2 + a3 + a4);
    const float g3 = 0.5f * (-a1 + a2 - a3 + a4);
    const float g4 = 0.5f * ( a1 - a2 - a3 + a4);
    const long rp = (long)b * Nn + p;
    float* k2r = k2 + rp * 1152;
    float* v2r = v2 + rp * 1152;
    if (c < 384) k1[rp * 384 + c] = g1; else k2r[c - 384] = g1;
    k2r[384 + c] = g2;
    if (c < 384) v1[rp * 384 + c] = g3; else v2r[c - 384] = g3;
    v2r[384 + c] = g4;
}

// ---------------------------------------------------------------------------
// IWT
// ---------------------------------------------------------------------------
__global__ void iwt_kernel(const float* __restrict__ x1,
                           const float* __restrict__ x2,
                           float* __restrict__ y)
{
    long idx = (long)blockIdx.x * blockDim.x + threadIdx.x;
    if (idx >= Bb * Ll * 384) return;
    const int c = (int)(idx % 384);
    const long tt = idx / 384;
    const int l = (int)(tt % Ll);
    const int b = (int)(tt / Ll);
    const int r = l >> 6, s = l & 63;
    const int i = r >> 1, j = s >> 1;
    const int p = r & 1, q = s & 1;
    const long pp = (long)b * Nn + (i * 32 + j);
    const float g1 = x1[pp * 384 + c];
    const float* x2r = x2 + pp * 1152;
    const float g2 = x2r[c];
    const float g3 = x2r[384 + c];
    const float g4 = x2r[768 + c];
    const float s2 = q ? 1.f : -1.f;
    const float s3 = p ? 1.f : -1.f;
    const float s4 = (p == q) ? 1.f : -1.f;
    y[idx] = 0.5f * (g1 + s2 * g2 + s3 * g3 + s4 * g4);
}

// ---------------------------------------------------------------------------
// launch
// ---------------------------------------------------------------------------
extern "C" void kernel_launch(void* const* d_in, const int* in_sizes, int n_in,
                              void* d_out, int out_size)
{
    const float* sf      = (const float*)d_in[0];
    const float* wf      = (const float*)d_in[1];
    const float* q_w     = (const float*)d_in[2];
    const float* q_b     = (const float*)d_in[3];
    const float* q_ln_w  = (const float*)d_in[4];
    const float* q_ln_b  = (const float*)d_in[5];
    const float* kv_w    = (const float*)d_in[6];
    const float* kv_b    = (const float*)d_in[7];
    const float* kv_ln_w = (const float*)d_in[8];
    const float* kv_ln_b = (const float*)d_in[9];
    const float* out_w   = (const float*)d_in[10];
    const float* out_b   = (const float*)d_in[11];
    float* out = (float*)d_out;

    float* scr = nullptr;
    cudaGetSymbolAddress((void**)&scr, g_scratch);
    float* t1 = scr + T1_OFF;
    float* t2 = scr + T2_OFF;
    float* q1 = scr + Q1_OFF;
    float* q2 = scr + Q2_OFF;
    float* k1 = scr + K1_OFF;
    float* k2 = scr + K2_OFF;
    float* v1 = scr + V1_OFF;
    float* v2 = scr + V2_OFF;
    float* Sm = scr + S_OFF;
    float* x1 = scr + X1_OFF;
    float* x2 = scr + X2_OFF;

    const float SCALE = 0.08838834764831845f;   // 1/sqrt(128)
    const long MB1 = 1048576L;

    // 1) t1 = sf @ q_w^T + q_b ; LN
    gemm_tc<false, true, true><<<dim3(3, 256, 1), 256>>>(
        sf, q_w, t1, q_b, 32768, 384, 384, 384, 384, 384, 1.f,
        1, 0, 0, 0, 0, 0, 0);
    ln_kernel<384><<<32768, 128>>>(t1, q_ln_w, q_ln_b);

    // 2) t2 = wf @ kv_w^T + kv_b ; LN
    gemm_tc<false, true, true><<<dim3(6, 256, 1), 256>>>(
        wf, kv_w, t2, kv_b, 32768, 768, 384, 384, 384, 768, 1.f,
        1, 0, 0, 0, 0, 0, 0);
    ln_kernel<768><<<32768, 128>>>(t2, kv_ln_w, kv_ln_b);

    // 3) DWT gathers
    dwt_sf_kernel<<<(unsigned)((Bb * Nn * 384 + 255) / 256), 256>>>(t1, q1, q2);
    dwt_wf_kernel<<<(unsigned)((Bb * Nn * 768 + 255) / 256), 256>>>(t2, k1, k2, v1, v2);

    // 4) att1 logits: S[b] = q1[b] @ k1[b]^T
    gemm_tc<false, true, false><<<dim3(8, 8, 8), 256>>>(
        q1, k1, Sm, nullptr, 1024, 1024, 384, 384, 384, 1024, 1.f,
        1, Nn * 384, 0, Nn * 384, 0, MB1, 0);

    // 5) att2 logits: S[8 + b*3+h] = q2_head @ k2_head^T * SCALE
    gemm_tc<false, true, false><<<dim3(8, 8, 24), 256>>>(
        q2, k2, Sm + 8 * MB1, nullptr, 1024, 1024, 384, 1152, 1152, 1024, SCALE,
        3, Nn * 1152, 384, Nn * 1152, 384, 3 * MB1, MB1);

    // 6) softmax over all 32*1024 rows
    softmax1024<<<32768, 256>>>(Sm);

    // 7) x1[b] = P1[b] @ v1[b]
    gemm_tc<false, false, false><<<dim3(3, 8, 8), 256>>>(
        Sm, v1, x1, nullptr, 1024, 384, 1024, 1024, 384, 384, 1.f,
        1, MB1, 0, Nn * 384, 0, Nn * 384, 0);

    // 8) x2_head = P2_head^T @ v2_head
    gemm_tc<true, false, false><<<dim3(3, 8, 24), 256>>>(
        Sm + 8 * MB1, v2, x2, nullptr, 1024, 384, 1024, 1024, 1152, 1152, 1.f,
        3, 3 * MB1, MB1, Nn * 1152, 384, Nn * 1152, 384);

    // 9) IWT -> y (reuse t1 slab)
    iwt_kernel<<<(unsigned)((Bb * Ll * 384 + 255) / 256), 256>>>(x1, x2, t1);

    // 10) out = y @ out_w^T + out_b
    gemm_tc<false, true, true><<<dim3(3, 256, 1), 256>>>(
        t1, out_w, out, out_b, 32768, 384, 384, 384, 384, 384, 1.f,
        1, 0, 0, 0, 0, 0, 0);
}

// round 7
// speedup vs baseline: 2.1361x; 2.1361x over previous
#include <cuda_runtime.h>
#include <cuda_bf16.h>
#include <math.h>
#include <stdint.h>

typedef __nv_bfloat16 bf16;

constexpr long Bb = 8;
constexpr long Ll = 4096;
constexpr long Nn = 1024;
constexpr long Mrows = Bb * Ll;
constexpr long MB1 = 1024L * 1024;

constexpr long SZ_T1 = Mrows * 384;
constexpr long SZ_T2 = Mrows * 768;
constexpr long SZ_Q1 = Bb * Nn * 384;
constexpr long SZ_Q2 = Bb * Nn * 1152;
constexpr long SZ_S  = 32 * MB1;
constexpr long SZ_P2T = 24 * MB1;

__device__ float g_t1[SZ_T1];
__device__ float g_t2[SZ_T2];
__device__ float g_v1f[SZ_Q1];
__device__ float g_v2f[SZ_Q2];
__device__ float g_S[SZ_S];
__device__ float g_x1[SZ_Q1];
__device__ float g_x2[SZ_Q2];

__device__ bf16 g_sf_h[SZ_T1],  g_sf_l[SZ_T1];
__device__ bf16 g_wf_h[SZ_T2],  g_wf_l[SZ_T2];
__device__ bf16 g_qw_h[384*384],  g_qw_l[384*384];
__device__ bf16 g_kvw_h[768*384], g_kvw_l[768*384];
__device__ bf16 g_ow_h[384*384],  g_ow_l[384*384];
__device__ bf16 g_q1_h[SZ_Q1],  g_q1_l[SZ_Q1];
__device__ bf16 g_q2_h[SZ_Q2],  g_q2_l[SZ_Q2];
__device__ bf16 g_k1_h[SZ_Q1],  g_k1_l[SZ_Q1];
__device__ bf16 g_k2_h[SZ_Q2],  g_k2_l[SZ_Q2];
__device__ bf16 g_v1t_h[SZ_Q1], g_v1t_l[SZ_Q1];
__device__ bf16 g_v2t_h[SZ_Q2], g_v2t_l[SZ_Q2];
__device__ bf16 g_P_h[SZ_S],    g_P_l[SZ_S];
__device__ bf16 g_p2t_h[SZ_P2T], g_p2t_l[SZ_P2T];
__device__ bf16 g_y_h[SZ_T1],   g_y_l[SZ_T1];

__device__ __forceinline__ float warp_sum(float v) {
    #pragma unroll
    for (int o = 16; o > 0; o >>= 1) v += __shfl_xor_sync(0xffffffffu, v, o);
    return v;
}
__device__ __forceinline__ float warp_max(float v) {
    #pragma unroll
    for (int o = 16; o > 0; o >>= 1) v = fmaxf(v, __shfl_xor_sync(0xffffffffu, v, o));
    return v;
}
__device__ __forceinline__ void bsplit(float v, bf16& h, bf16& l) {
    h = __float2bfloat16(v);
    l = __float2bfloat16(v - __bfloat162float(h));
}
__device__ __forceinline__ void ldsm4(uint32_t* r, uint32_t a) {
    asm volatile("ldmatrix.sync.aligned.m8n8.x4.shared.b16 {%0,%1,%2,%3}, [%4];"
        : "=r"(r[0]), "=r"(r[1]), "=r"(r[2]), "=r"(r[3]) : "r"(a));
}
__device__ __forceinline__ void mma16(float* c, const uint32_t* a, uint32_t b0, uint32_t b1) {
    asm volatile("mma.sync.aligned.m16n8k16.row.col.f32.bf16.bf16.f32 "
        "{%0,%1,%2,%3},{%4,%5,%6,%7},{%8,%9},{%0,%1,%2,%3};"
        : "+f"(c[0]), "+f"(c[1]), "+f"(c[2]), "+f"(c[3])
        : "r"(a[0]), "r"(a[1]), "r"(a[2]), "r"(a[3]), "r"(b0), "r"(b1));
}
__device__ __forceinline__ void cp16(uint32_t dst, const void* src) {
    asm volatile("cp.async.cg.shared.global [%0], [%1], 16;" :: "r"(dst), "l"(src));
}

// ---------------------------------------------------------------------------
// TN bf16 split GEMM: C[m,n] = alpha * sum_k A[m,k]*B[n,k] (+bias[n])
// A,B are hi/lo bf16 plane pairs, row-major. 128x128x16 tile, 256 thr.
// ---------------------------------------------------------------------------
#define SROW 24

template<bool BIAS>
__global__ __launch_bounds__(256) void gemm_bf16(
    const bf16* __restrict__ Ah, const bf16* __restrict__ Al,
    const bf16* __restrict__ Bh, const bf16* __restrict__ Bl,
    float* __restrict__ Cp, const float* __restrict__ bias,
    int K, int lda, int ldb, int ldc, float alpha,
    int nh, long bsA, long hsA, long bsB, long hsB, long bsC, long hsC)
{
    const int z = blockIdx.z;
    const int bbi = z / nh, hh = z % nh;
    const long offA = bbi * bsA + hh * hsA;
    const long offB = bbi * bsB + hh * hsB;
    Ah += offA; Al += offA;
    Bh += offB; Bl += offB;
    Cp += bbi * bsC + hh * hsC;

    __shared__ __align__(16) bf16 sAh[2][128 * SROW], sAl[2][128 * SROW];
    __shared__ __align__(16) bf16 sBh[2][128 * SROW], sBl[2][128 * SROW];

    const int tid  = threadIdx.x;
    const int lane = tid & 31;
    const int warp = tid >> 5;
    const int wm = (warp & 1) * 64;
    const int wn = (warp >> 1) * 32;
    const long m0 = (long)blockIdx.y * 128;
    const long n0 = (long)blockIdx.x * 128;

    uint32_t bAh[2], bAl[2], bBh[2], bBl[2];
    #pragma unroll
    for (int s = 0; s < 2; s++) {
        bAh[s] = (uint32_t)__cvta_generic_to_shared(&sAh[s][0]);
        bAl[s] = (uint32_t)__cvta_generic_to_shared(&sAl[s][0]);
        bBh[s] = (uint32_t)__cvta_generic_to_shared(&sBh[s][0]);
        bBl[s] = (uint32_t)__cvta_generic_to_shared(&sBl[s][0]);
    }

    const int lr = tid >> 1, lh = tid & 1;
    const uint32_t sm_off = (uint32_t)(lr * SROW + lh * 8) * 2u;

    auto issue = [&](int k0, int st) {
        const long ga = (m0 + lr) * (long)lda + k0 + lh * 8;
        const long gb = (n0 + lr) * (long)ldb + k0 + lh * 8;
        cp16(bAh[st] + sm_off, Ah + ga);
        cp16(bAl[st] + sm_off, Al + ga);
        cp16(bBh[st] + sm_off, Bh + gb);
        cp16(bBl[st] + sm_off, Bl + gb);
        asm volatile("cp.async.commit_group;");
    };

    const uint32_t aoff = (uint32_t)((wm + (lane & 7) + ((lane >> 3) & 1) * 8) * SROW
                                     + (lane >> 4) * 8) * 2u;
    const uint32_t boff = (uint32_t)((wn + (lane & 7) + (lane >> 4) * 8) * SROW
                                     + ((lane >> 3) & 1) * 8) * 2u;

    float acc[4][4][4];
    #pragma unroll
    for (int i = 0; i < 4; i++)
        #pragma unroll
        for (int j = 0; j < 4; j++)
            #pragma unroll
            for (int e = 0; e < 4; e++) acc[i][j][e] = 0.f;

    const int nit = K / 16;
    int st = 0;
    issue(0, 0);
    for (int it = 0; it < nit; ++it) {
        asm volatile("cp.async.wait_group 0;" ::: "memory");
        __syncthreads();
        if (it + 1 < nit) issue((it + 1) * 16, st ^ 1);

        uint32_t ah[4][4], al[4][4], bh[2][4], bl[2][4];
        #pragma unroll
        for (int mt = 0; mt < 4; mt++) {
            const uint32_t o = aoff + (uint32_t)(mt * 16 * SROW) * 2u;
            ldsm4(ah[mt], bAh[st] + o);
            ldsm4(al[mt], bAl[st] + o);
        }
        #pragma unroll
        for (int ng = 0; ng < 2; ng++) {
            const uint32_t o = boff + (uint32_t)(ng * 16 * SROW) * 2u;
            ldsm4(bh[ng], bBh[st] + o);
            ldsm4(bl[ng], bBl[st] + o);
        }
        #pragma unroll
        for (int mt = 0; mt < 4; mt++) {
            #pragma unroll
            for (int nt = 0; nt < 4; nt++) {
                const uint32_t* fh = &bh[nt >> 1][(nt & 1) * 2];
                const uint32_t* fl = &bl[nt >> 1][(nt & 1) * 2];
                mma16(acc[mt][nt], ah[mt], fh[0], fh[1]);
                mma16(acc[mt][nt], ah[mt], fl[0], fl[1]);
                mma16(acc[mt][nt], al[mt], fh[0], fh[1]);
            }
        }
        st ^= 1;
        __syncthreads();
    }

    #pragma unroll
    for (int mt = 0; mt < 4; mt++) {
        const long r0 = m0 + wm + mt * 16 + (lane >> 2);
        #pragma unroll
        for (int nt = 0; nt < 4; nt++) {
            const long cc = n0 + wn + nt * 8 + (lane & 3) * 2;
            float b0 = 0.f, b1 = 0.f;
            if (BIAS) { b0 = bias[cc]; b1 = bias[cc + 1]; }
            float2 v;
            v.x = acc[mt][nt][0] * alpha + b0;
            v.y = acc[mt][nt][1] * alpha + b1;
            *reinterpret_cast<float2*>(Cp + r0 * ldc + cc) = v;
            v.x = acc[mt][nt][2] * alpha + b0;
            v.y = acc[mt][nt][3] * alpha + b1;
            *reinterpret_cast<float2*>(Cp + (r0 + 8) * ldc + cc) = v;
        }
    }
}

// fp32 -> bf16 hi/lo planes
__global__ void convert_cv(const float* __restrict__ in,
                           bf16* __restrict__ oh, bf16* __restrict__ ol, long n)
{
    long i4 = ((long)blockIdx.x * blockDim.x + threadIdx.x) * 4;
    if (i4 >= n) return;
    float4 v = *reinterpret_cast<const float4*>(in + i4);
    bf16 h, l;
    bsplit(v.x, h, l); oh[i4 + 0] = h; ol[i4 + 0] = l;
    bsplit(v.y, h, l); oh[i4 + 1] = h; ol[i4 + 1] = l;
    bsplit(v.z, h, l); oh[i4 + 2] = h; ol[i4 + 2] = l;
    bsplit(v.w, h, l); oh[i4 + 3] = h; ol[i4 + 3] = l;
}

template<int W>
__global__ __launch_bounds__(128) void ln_kernel(float* __restrict__ x,
                                                 const float* __restrict__ g,
                                                 const float* __restrict__ b)
{
    constexpr int TPB = 128, PER = W / TPB;
    float* xr = x + (long)blockIdx.x * W;
    const int t = threadIdx.x;
    float v[PER];
    float s = 0.f, s2 = 0.f;
    #pragma unroll
    for (int i = 0; i < PER; i++) {
        v[i] = xr[t + i * TPB];
        s += v[i]; s2 += v[i] * v[i];
    }
    __shared__ float shA[4], shB[4];
    s = warp_sum(s); s2 = warp_sum(s2);
    if ((t & 31) == 0) { shA[t >> 5] = s; shB[t >> 5] = s2; }
    __syncthreads();
    s  = shA[0] + shA[1] + shA[2] + shA[3];
    s2 = shB[0] + shB[1] + shB[2] + shB[3];
    const float mean = s / W;
    const float var  = s2 / W - mean * mean;
    const float inv  = rsqrtf(var + 1e-5f);
    #pragma unroll
    for (int i = 0; i < PER; i++) {
        const int c = t + i * TPB;
        xr[c] = (v[i] - mean) * inv * g[c] + b[c];
    }
}

// softmax over 1024 cols -> bf16 hi/lo planes
__global__ __launch_bounds__(256) void softmax1024(const float* __restrict__ S,
                                                   bf16* __restrict__ Ph,
                                                   bf16* __restrict__ Pl)
{
    const long ro = (long)blockIdx.x * 1024;
    const float* row = S + ro;
    const int t = threadIdx.x;
    float v[4];
    float mx = -1e30f;
    #pragma unroll
    for (int i = 0; i < 4; i++) { v[i] = row[t + i * 256]; mx = fmaxf(mx, v[i]); }
    __shared__ float shm[8], shs[8];
    mx = warp_max(mx);
    if ((t & 31) == 0) shm[t >> 5] = mx;
    __syncthreads();
    float rmax = shm[0];
    #pragma unroll
    for (int i = 1; i < 8; i++) rmax = fmaxf(rmax, shm[i]);
    float s = 0.f;
    #pragma unroll
    for (int i = 0; i < 4; i++) { v[i] = expf(v[i] - rmax); s += v[i]; }
    s = warp_sum(s);
    if ((t & 31) == 0) shs[t >> 5] = s;
    __syncthreads();
    float rs = 0.f;
    #pragma unroll
    for (int i = 0; i < 8; i++) rs += shs[i];
    const float inv = 1.f / rs;
    #pragma unroll
    for (int i = 0; i < 4; i++) {
        bf16 h, l;
        bsplit(v[i] * inv, h, l);
        Ph[ro + t + i * 256] = h;
        Pl[ro + t + i * 256] = l;
    }
}

// DWT: t1 -> q1,q2 planes
__global__ void dwt_sf_kernel(const float* __restrict__ t1,
                              bf16* __restrict__ q1h, bf16* __restrict__ q1l,
                              bf16* __restrict__ q2h, bf16* __restrict__ q2l)
{
    long idx = (long)blockIdx.x * blockDim.x + threadIdx.x;
    if (idx >= Bb * Nn * 384) return;
    const int c = (int)(idx % 384);
    const long tt = idx / 384;
    const int p = (int)(tt % Nn);
    const int b = (int)(tt / Nn);
    const int i = p >> 5, j = p & 31;
    const long base = (long)b * Ll * 384 + c;
    const float a1 = t1[base + (long)((2 * i)     * 64 + 2 * j)     * 384];
    const float a2 = t1[base + (long)((2 * i + 1) * 64 + 2 * j)     * 384];
    const float a3 = t1[base + (long)((2 * i)     * 64 + 2 * j + 1) * 384];
    const float a4 = t1[base + (long)((2 * i + 1) * 64 + 2 * j + 1) * 384];
    const float g1 = 0.5f * ( a1 + a2 + a3 + a4);
    const float g2 = 0.5f * (-a1 - a2 + a3 + a4);
    const float g3 = 0.5f * (-a1 + a2 - a3 + a4);
    const float g4 = 0.5f * ( a1 - a2 - a3 + a4);
    const long rp = (long)b * Nn + p;
    bf16 h, l;
    bsplit(g1, h, l); q1h[rp * 384 + c] = h; q1l[rp * 384 + c] = l;
    const long q2o = rp * 1152;
    bsplit(g2, h, l); q2h[q2o + c] = h;       q2l[q2o + c] = l;
    bsplit(g3, h, l); q2h[q2o + 384 + c] = h; q2l[q2o + 384 + c] = l;
    bsplit(g4, h, l); q2h[q2o + 768 + c] = h; q2l[q2o + 768 + c] = l;
}

// DWT: t2 -> k1,k2 planes; v1,v2 fp32
__global__ void dwt_wf_kernel(const float* __restrict__ t2,
                              bf16* __restrict__ k1h, bf16* __restrict__ k1l,
                              bf16* __restrict__ k2h, bf16* __restrict__ k2l,
                              float* __restrict__ v1f, float* __restrict__ v2f)
{
    long idx = (long)blockIdx.x * blockDim.x + threadIdx.x;
    if (idx >= Bb * Nn * 768) return;
    const int c = (int)(idx % 768);
    const long tt = idx / 768;
    const int p = (int)(tt % Nn);
    const int b = (int)(tt / Nn);
    const int i = p >> 5, j = p & 31;
    const long base = (long)b * Ll * 768 + c;
    const float a1 = t2[base + (long)((2 * i)     * 64 + 2 * j)     * 768];
    const float a2 = t2[base + (long)((2 * i + 1) * 64 + 2 * j)     * 768];
    const float a3 = t2[base + (long)((2 * i)     * 64 + 2 * j + 1) * 768];
    const float a4 = t2[base + (long)((2 * i + 1) * 64 + 2 * j + 1) * 768];
    const float g1 = 0.5f * ( a1 + a2 + a3 + a4);
    const float g2 = 0.5f * (-a1 - a2 + a3 + a4);
    const float g3 = 0.5f * (-a1 + a2 - a3 + a4);
    const float g4 = 0.5f * ( a1 - a2 - a3 + a4);
    const long rp = (long)b * Nn + p;
    bf16 h, l;
    if (c < 384) { bsplit(g1, h, l); k1h[rp * 384 + c] = h; k1l[rp * 384 + c] = l; }
    else         { bsplit(g1, h, l); k2h[rp * 1152 + c - 384] = h; k2l[rp * 1152 + c - 384] = l; }
    bsplit(g2, h, l); k2h[rp * 1152 + 384 + c] = h; k2l[rp * 1152 + 384 + c] = l;
    if (c < 384) v1f[rp * 384 + c] = g3; else v2f[rp * 1152 + c - 384] = g3;
    v2f[rp * 1152 + 384 + c] = g4;
}

// transpose+split fp32 [1024][cols] per z -> bf16 planes [cols][1024]
__global__ __launch_bounds__(256) void vtrans(const float* __restrict__ in,
                                              bf16* __restrict__ oh,
                                              bf16* __restrict__ ol, int cols)
{
    const long zo = (long)blockIdx.z * 1024L * cols;
    const int c0 = blockIdx.x * 64, r0 = blockIdx.y * 64;
    __shared__ float tf[64][65];
    const int tid = threadIdx.x;
    #pragma unroll
    for (int j = 0; j < 16; j++) {
        const int e = tid + j * 256;
        const int r = e >> 6, c = e & 63;
        tf[r][c] = in[zo + (long)(r0 + r) * cols + c0 + c];
    }
    __syncthreads();
    #pragma unroll
    for (int j = 0; j < 16; j++) {
        const int e = tid + j * 256;
        const int c = e >> 6, r = e & 63;
        bf16 h, l;
        bsplit(tf[r][c], h, l);
        const long oi = zo + (long)(c0 + c) * 1024 + r0 + r;
        oh[oi] = h; ol[oi] = l;
    }
}

// transpose bf16 plane pair, per z slab 1024x1024
__global__ __launch_bounds__(256) void ptrans(const bf16* __restrict__ ih,
                                              const bf16* __restrict__ il,
                                              bf16* __restrict__ oh,
                                              bf16* __restrict__ ol)
{
    const long zo = (long)blockIdx.z * MB1;
    const int r0 = blockIdx.y * 64, c0 = blockIdx.x * 64;
    __shared__ bf16 th[64][66], tl[64][66];
    const int tid = threadIdx.x;
    #pragma unroll
    for (int j = 0; j < 8; j++) {
        const int e = tid + j * 256;
        const int r = e >> 5, c2 = e & 31;
        const long gi = zo + (long)(r0 + r) * 1024 + c0 + c2 * 2;
        __nv_bfloat162 vh = *reinterpret_cast<const __nv_bfloat162*>(ih + gi);
        __nv_bfloat162 vl = *reinterpret_cast<const __nv_bfloat162*>(il + gi);
        th[r][c2 * 2] = vh.x; th[r][c2 * 2 + 1] = vh.y;
        tl[r][c2 * 2] = vl.x; tl[r][c2 * 2 + 1] = vl.y;
    }
    __syncthreads();
    #pragma unroll
    for (int j = 0; j < 8; j++) {
        const int e = tid + j * 256;
        const int c = e >> 5, r2 = e & 31;
        const long oi = zo + (long)(c0 + c) * 1024 + r0 + r2 * 2;
        __nv_bfloat162 v;
        v.x = th[r2 * 2][c]; v.y = th[r2 * 2 + 1][c];
        *reinterpret_cast<__nv_bfloat162*>(oh + oi) = v;
        v.x = tl[r2 * 2][c]; v.y = tl[r2 * 2 + 1][c];
        *reinterpret_cast<__nv_bfloat162*>(ol + oi) = v;
    }
}

// IWT -> y planes
__global__ void iwt_kernel(const float* __restrict__ x1,
                           const float* __restrict__ x2,
                           bf16* __restrict__ yh, bf16* __restrict__ yl)
{
    long idx = (long)blockIdx.x * blockDim.x + threadIdx.x;
    if (idx >= Bb * Ll * 384) return;
    const int c = (int)(idx % 384);
    const long tt = idx / 384;
    const int l = (int)(tt % Ll);
    const int b = (int)(tt / Ll);
    const int r = l >> 6, s = l & 63;
    const int i = r >> 1, j = s >> 1;
    const int p = r & 1, q = s & 1;
    const long pp = (long)b * Nn + (i * 32 + j);
    const float g1 = x1[pp * 384 + c];
    const float* x2r = x2 + pp * 1152;
    const float g2 = x2r[c];
    const float g3 = x2r[384 + c];
    const float g4 = x2r[768 + c];
    const float s2 = q ? 1.f : -1.f;
    const float s3 = p ? 1.f : -1.f;
    const float s4 = (p == q) ? 1.f : -1.f;
    bf16 h, lo;
    bsplit(0.5f * (g1 + s2 * g2 + s3 * g3 + s4 * g4), h, lo);
    yh[idx] = h; yl[idx] = lo;
}

extern "C" void kernel_launch(void* const* d_in, const int* in_sizes, int n_in,
                              void* d_out, int out_size)
{
    const float* sf      = (const float*)d_in[0];
    const float* wf      = (const float*)d_in[1];
    const float* q_w     = (const float*)d_in[2];
    const float* q_b     = (const float*)d_in[3];
    const float* q_ln_w  = (const float*)d_in[4];
    const float* q_ln_b  = (const float*)d_in[5];
    const float* kv_w    = (const float*)d_in[6];
    const float* kv_b    = (const float*)d_in[7];
    const float* kv_ln_w = (const float*)d_in[8];
    const float* kv_ln_b = (const float*)d_in[9];
    const float* out_w   = (const float*)d_in[10];
    const float* out_b   = (const float*)d_in[11];
    float* out = (float*)d_out;

    #define GETF(sym, var) float* var; cudaGetSymbolAddress((void**)&var, sym)
    #define GETB(sym, var) bf16*  var; cudaGetSymbolAddress((void**)&var, sym)
    GETF(g_t1, t1);   GETF(g_t2, t2);
    GETF(g_v1f, v1f); GETF(g_v2f, v2f);
    GETF(g_S, S);     GETF(g_x1, x1);  GETF(g_x2, x2);
    GETB(g_sf_h, sfh);   GETB(g_sf_l, sfl);
    GETB(g_wf_h, wfh);   GETB(g_wf_l, wfl);
    GETB(g_qw_h, qwh);   GETB(g_qw_l, qwl);
    GETB(g_kvw_h, kvwh); GETB(g_kvw_l, kvwl);
    GETB(g_ow_h, owh);   GETB(g_ow_l, owl);
    GETB(g_q1_h, q1h);   GETB(g_q1_l, q1l);
    GETB(g_q2_h, q2h);   GETB(g_q2_l, q2l);
    GETB(g_k1_h, k1h);   GETB(g_k1_l, k1l);
    GETB(g_k2_h, k2h);   GETB(g_k2_l, k2l);
    GETB(g_v1t_h, v1th); GETB(g_v1t_l, v1tl);
    GETB(g_v2t_h, v2th); GETB(g_v2t_l, v2tl);
    GETB(g_P_h, Ph);     GETB(g_P_l, Pl);
    GETB(g_p2t_h, p2th); GETB(g_p2t_l, p2tl);
    GETB(g_y_h, yh);     GETB(g_y_l, yl);
    #undef GETF
    #undef GETB

    const float SCALE = 0.08838834764831845f;   // 1/sqrt(128)
    auto cvb = [](long n) { return (unsigned)((n / 4 + 255) / 256); };

    // 0) pre-split inputs + weights
    convert_cv<<<cvb(SZ_T1), 256>>>(sf, sfh, sfl, SZ_T1);
    convert_cv<<<cvb(SZ_T2), 256>>>(wf, wfh, wfl, SZ_T2);
    convert_cv<<<cvb(384 * 384), 256>>>(q_w, qwh, qwl, 384 * 384);
    convert_cv<<<cvb(768 * 384), 256>>>(kv_w, kvwh, kvwl, 768 * 384);
    convert_cv<<<cvb(384 * 384), 256>>>(out_w, owh, owl, 384 * 384);

    // 1) t1 = sf @ q_w^T + q_b ; LN
    gemm_bf16<true><<<dim3(3, 256, 1), 256>>>(
        sfh, sfl, qwh, qwl, t1, q_b, 384, 384, 384, 384, 1.f,
        1, 0, 0, 0, 0, 0, 0);
    ln_kernel<384><<<32768, 128>>>(t1, q_ln_w, q_ln_b);

    // 2) t2 = wf @ kv_w^T + kv_b ; LN
    gemm_bf16<true><<<dim3(6, 256, 1), 256>>>(
        wfh, wfl, kvwh, kvwl, t2, kv_b, 384, 384, 384, 768, 1.f,
        1, 0, 0, 0, 0, 0, 0);
    ln_kernel<768><<<32768, 128>>>(t2, kv_ln_w, kv_ln_b);

    // 3) DWT gathers (+ split)
    dwt_sf_kernel<<<(unsigned)((Bb * Nn * 384 + 255) / 256), 256>>>(t1, q1h, q1l, q2h, q2l);
    dwt_wf_kernel<<<(unsigned)((Bb * Nn * 768 + 255) / 256), 256>>>(t2, k1h, k1l, k2h, k2l, v1f, v2f);

    // 4) V transposes (+ split)
    vtrans<<<dim3(6, 16, 8), 256>>>(v1f, v1th, v1tl, 384);
    vtrans<<<dim3(18, 16, 8), 256>>>(v2f, v2th, v2tl, 1152);

    // 5) att1 logits
    gemm_bf16<false><<<dim3(8, 8, 8), 256>>>(
        q1h, q1l, k1h, k1l, S, nullptr, 384, 384, 384, 1024, 1.f,
        1, Nn * 384, 0, Nn * 384, 0, MB1, 0);

    // 6) att2 logits
    gemm_bf16<false><<<dim3(8, 8, 24), 256>>>(
        q2h, q2l, k2h, k2l, S + 8 * MB1, nullptr, 384, 1152, 1152, 1024, SCALE,
        3, Nn * 1152, 384, Nn * 1152, 384, 3 * MB1, MB1);

    // 7) softmax -> P planes
    softmax1024<<<32768, 256>>>(S, Ph, Pl);

    // 8) P2^T planes
    ptrans<<<dim3(16, 16, 24), 256>>>(Ph + 8 * MB1, Pl + 8 * MB1, p2th, p2tl);

    // 9) x1 = P1 @ V1   (B as V1^T planes, TN form)
    gemm_bf16<false><<<dim3(3, 8, 8), 256>>>(
        Ph, Pl, v1th, v1tl, x1, nullptr, 1024, 1024, 1024, 384, 1.f,
        1, MB1, 0, 384 * 1024, 0, Nn * 384, 0);

    // 10) x2 = P2^T @ V2   (A = p2t, B = V2^T planes)
    gemm_bf16<false><<<dim3(3, 8, 24), 256>>>(
        p2th, p2tl, v2th, v2tl, x2, nullptr, 1024, 1024, 1024, 1152, 1.f,
        3, 3 * MB1, MB1, 1152 * 1024, 384 * 1024, Nn * 1152, 384);

    // 11) IWT -> y planes
    iwt_kernel<<<(unsigned)((Bb * Ll * 384 + 255) / 256), 256>>>(x1, x2, yh, yl);

    // 12) out = y @ out_w^T + out_b
    gemm_bf16<true><<<dim3(3, 256, 1), 256>>>(
        yh, yl, owh, owl, out, out_b, 384, 384, 384, 384, 1.f,
        1, 0, 0, 0, 0, 0, 0);
}